// round 14
// baseline (speedup 1.0000x reference)
#include <cuda_runtime.h>
#include <cuda_fp16.h>
#include <cstdint>

#define D    1024
#define E    8
#define FF   4096
#define CAP  2048
#define T    8192
#define W_IMP    0.01f
#define W_LOAD   0.01f
#define LAMBDA_Z 0.001f
#define W_PEN    0.01f

// ---------------- device scratch ---------------------------------------------
__device__ int   g_e1[T], g_e2[T];
__device__ float g_g1n[T], g_g2n[T];
__device__ float g_ws[2][T];
__device__ int   g_idx[2][E * CAP];
__device__ int   g_cnt[2][E];
__device__ float g_part[(T / 8) * 26];
__device__ float g_red[26];
__device__ __half g_Hh[(size_t)2 * E * CAP * FF];
__device__ __half g_Xh[(size_t)T * D];
__device__ __half g_W1h[(size_t)E * D * FF];
__device__ __half g_W2h[(size_t)E * FF * D];

// ---------------- helpers ----------------------------------------------------
__device__ __forceinline__ uint32_t smem_u32(const void* p) {
    uint32_t a;
    asm("{ .reg .u64 t; cvta.to.shared.u64 t, %1; cvt.u32.u64 %0, t; }" : "=r"(a) : "l"(p));
    return a;
}
__device__ __forceinline__ float gelu_tanh(float v) {
    const float c = 0.7978845608028654f;
    float u = c * (v + 0.044715f * v * v * v);
    return 0.5f * v * (1.0f + tanhf(u));
}
__device__ __forceinline__ void cp16(uint32_t s, const void* g, uint32_t ssz) {
    asm volatile("cp.async.cg.shared.global [%0], [%1], 16, %2;"
                 :: "r"(s), "l"(g), "r"(ssz));
}
__device__ __forceinline__ void ldsm4(uint32_t* r, uint32_t addr) {
    asm volatile("ldmatrix.sync.aligned.m8n8.x4.shared.b16 {%0,%1,%2,%3}, [%4];"
                 : "=r"(r[0]), "=r"(r[1]), "=r"(r[2]), "=r"(r[3]) : "r"(addr));
}
__device__ __forceinline__ void ldsm4t(uint32_t* r, uint32_t addr) {
    asm volatile("ldmatrix.sync.aligned.m8n8.x4.trans.shared.b16 {%0,%1,%2,%3}, [%4];"
                 : "=r"(r[0]), "=r"(r[1]), "=r"(r[2]), "=r"(r[3]) : "r"(addr));
}
__device__ __forceinline__ void mma16816(float* c, const uint32_t* a, const uint32_t* b) {
    asm volatile("mma.sync.aligned.m16n8k16.row.col.f32.f16.f16.f32 "
                 "{%0,%1,%2,%3}, {%4,%5,%6,%7}, {%8,%9}, {%0,%1,%2,%3};"
                 : "+f"(c[0]), "+f"(c[1]), "+f"(c[2]), "+f"(c[3])
                 : "r"(a[0]), "r"(a[1]), "r"(a[2]), "r"(a[3]), "r"(b[0]), "r"(b[1]));
}
__device__ __forceinline__ void redadd(float* p, float v) {
    asm volatile("red.global.add.f32 [%0], %1;" :: "l"(p), "f"(v) : "memory");
}

// ---------------- fused prologue: gate + f2h(x, w1) --------------------------
#define GATE_BLKS 1024
#define X4  (T * D / 4)
#define W4  (E * D * FF / 4)
#define F2H_TOTAL (X4 + W4)
#define F2H_BLKS (F2H_TOTAL / 1024)

__global__ void prologue_kernel(const float* __restrict__ x, const float* __restrict__ gw,
                                const float* __restrict__ w1,
                                __half* __restrict__ xh, __half* __restrict__ w1h) {
    if (blockIdx.x >= GATE_BLKS) {
        size_t base = (size_t)(blockIdx.x - GATE_BLKS) * 1024 + threadIdx.x;
#pragma unroll
        for (int i = 0; i < 4; i++) {
            size_t c = base + (size_t)i * 256;
            const float4* src; __half2* dst;
            if (c < X4) { src = (const float4*)x  + c;        dst = (__half2*)xh  + c * 2; }
            else        { src = (const float4*)w1 + (c - X4); dst = (__half2*)w1h + (c - X4) * 2; }
            float4 v = *src;
            dst[0] = __floats2half2_rn(v.x, v.y);
            dst[1] = __floats2half2_rn(v.z, v.w);
        }
        return;
    }
    __shared__ float sgw[E * D];
    __shared__ float wpart[8][26];
    int tid = threadIdx.x;
    for (int i = tid; i < E * D; i += 256) sgw[i] = gw[i];
    __syncthreads();
    int warp = tid >> 5, lane = tid & 31;
    int t = blockIdx.x * 8 + warp;
    float acc[E];
#pragma unroll
    for (int e = 0; e < E; e++) acc[e] = 0.f;
    const float* xr = x + (size_t)t * D;
#pragma unroll 4
    for (int j = 0; j < D / 32; j++) {
        float xv = xr[j * 32 + lane];
#pragma unroll
        for (int e = 0; e < E; e++) acc[e] += xv * sgw[e * D + j * 32 + lane];
    }
#pragma unroll
    for (int e = 0; e < E; e++)
#pragma unroll
        for (int off = 16; off; off >>= 1)
            acc[e] += __shfl_xor_sync(0xffffffffu, acc[e], off);
    float m = acc[0];
#pragma unroll
    for (int e = 1; e < E; e++) m = fmaxf(m, acc[e]);
    float p166[E]; float s166 = 0.f;
#pragma unroll
    for (int e = 0; e < E; e++) { p166[e] = expf((acc[e] - m) / 1.66f); s166 += p166[e]; }
    float pa = 0.f;
#pragma unroll
    for (int e = 0; e < E; e++) { p166[e] /= s166; pa += p166[e] * (1.f - p166[e]); }
    float p[E]; float s = 0.f;
#pragma unroll
    for (int e = 0; e < E; e++) { p[e] = expf(acc[e] - m); s += p[e]; }
    float lse = m + logf(s);
#pragma unroll
    for (int e = 0; e < E; e++) p[e] /= s;
    int e1 = 0; float p1 = p[0];
#pragma unroll
    for (int e = 1; e < E; e++) if (p[e] > p1) { p1 = p[e]; e1 = e; }
    int e2 = -1; float p2 = -1.f;
#pragma unroll
    for (int e = 0; e < E; e++) if (e != e1 && p[e] > p2) { p2 = p[e]; e2 = e; }
    float den = p1 + p2;
    if (lane == 0) {
        g_e1[t] = e1; g_e2[t] = e2;
        g_g1n[t] = p1 / den; g_g2n[t] = p2 / den;
        wpart[warp][0] = pa;
#pragma unroll
        for (int e = 0; e < E; e++) wpart[warp][1 + e] = p166[e];
        wpart[warp][9] = lse * lse;
#pragma unroll
        for (int e = 0; e < E; e++) wpart[warp][10 + e] = p[e];
#pragma unroll
        for (int e = 0; e < E; e++) wpart[warp][18 + e] = (e == e1) ? 1.f : 0.f;
    }
    __syncthreads();
    if (tid < 26) {
        float sum = 0.f;
        for (int w = 0; w < 8; w++) sum += wpart[w][tid];
        g_part[blockIdx.x * 26 + tid] = sum;
    }
}

// ---------------- scan (+ reduce + aux fused) --------------------------------
__global__ void scan_kernel(const float* __restrict__ rnd, float* __restrict__ out) {
    __shared__ int s[E][1024];
    int tid = threadIdx.x;
    if (tid < 26) {
        float sum = 0.f;
        for (int b = 0; b < T / 8; b++) sum += g_part[b * 26 + tid];
        g_red[tid] = sum;
    }
    for (int i = tid; i < 2 * E * CAP; i += 1024) ((int*)g_idx)[i] = -1;
    int t0 = tid * 8;

    // ---- slot 1 ----
    int ev[8];
#pragma unroll
    for (int j = 0; j < 8; j++) ev[j] = g_e1[t0 + j];
    int c[E];
#pragma unroll
    for (int e = 0; e < E; e++) c[e] = 0;
#pragma unroll
    for (int j = 0; j < 8; j++) c[ev[j]]++;
#pragma unroll
    for (int e = 0; e < E; e++) s[e][tid] = c[e];
    __syncthreads();
    for (int off = 1; off < 1024; off <<= 1) {
        int r[E];
#pragma unroll
        for (int e = 0; e < E; e++) r[e] = (tid >= off) ? s[e][tid - off] : 0;
        __syncthreads();
#pragma unroll
        for (int e = 0; e < E; e++) s[e][tid] += r[e];
        __syncthreads();
    }
    int excl[E], tot[E];
#pragma unroll
    for (int e = 0; e < E; e++) { excl[e] = s[e][tid] - c[e]; tot[e] = s[e][1023]; }
    float impL[E];
#pragma unroll
    for (int e = 0; e < E; e++) impL[e] = 0.f;
#pragma unroll
    for (int j = 0; j < 8; j++) {
        int t = t0 + j, e = ev[j];
        int p = excl[e]++;
        bool mk = p < CAP;
        float w = mk ? g_g1n[t] : 0.f;
        g_ws[0][t] = w;
        if (mk) g_idx[0][e * CAP + p] = t;
        impL[e] += w;
    }
    if (tid == 0)
        for (int e = 0; e < E; e++) g_cnt[0][e] = tot[e] < CAP ? tot[e] : CAP;
    __syncthreads();

    // ---- slot 2, pass 1 ----
#pragma unroll
    for (int j = 0; j < 8; j++) ev[j] = g_e2[t0 + j];
#pragma unroll
    for (int e = 0; e < E; e++) c[e] = 0;
#pragma unroll
    for (int j = 0; j < 8; j++) c[ev[j]]++;
#pragma unroll
    for (int e = 0; e < E; e++) s[e][tid] = c[e];
    __syncthreads();
    for (int off = 1; off < 1024; off <<= 1) {
        int r[E];
#pragma unroll
        for (int e = 0; e < E; e++) r[e] = (tid >= off) ? s[e][tid - off] : 0;
        __syncthreads();
#pragma unroll
        for (int e = 0; e < E; e++) s[e][tid] += r[e];
        __syncthreads();
    }
#pragma unroll
    for (int e = 0; e < E; e++) excl[e] = s[e][tid] - c[e];
    bool live[8];
#pragma unroll
    for (int j = 0; j < 8; j++) {
        int t = t0 + j, e = ev[j];
        int p = excl[e]++;
        float g2n = g_g2n[t];
        bool mk = (p < CAP) && (rnd[t] < 2.f * g2n);
        live[j] = mk;
        float w = mk ? g2n : 0.f;
        g_ws[1][t] = w;
        impL[e] += w;
    }
    __syncthreads();

    // ---- slot 2, pass 2: compacted ----
#pragma unroll
    for (int e = 0; e < E; e++) c[e] = 0;
#pragma unroll
    for (int j = 0; j < 8; j++) if (live[j]) c[ev[j]]++;
#pragma unroll
    for (int e = 0; e < E; e++) s[e][tid] = c[e];
    __syncthreads();
    for (int off = 1; off < 1024; off <<= 1) {
        int r[E];
#pragma unroll
        for (int e = 0; e < E; e++) r[e] = (tid >= off) ? s[e][tid - off] : 0;
        __syncthreads();
#pragma unroll
        for (int e = 0; e < E; e++) s[e][tid] += r[e];
        __syncthreads();
    }
#pragma unroll
    for (int e = 0; e < E; e++) { excl[e] = s[e][tid] - c[e]; tot[e] = s[e][1023]; }
#pragma unroll
    for (int j = 0; j < 8; j++) {
        if (!live[j]) continue;
        int t = t0 + j, e = ev[j];
        int p = excl[e]++;
        g_idx[1][e * CAP + p] = t;
    }
    if (tid == 0)
        for (int e = 0; e < E; e++) g_cnt[1][e] = tot[e];
    __syncthreads();

    // ---- imp reduction + aux ----
    float* f = (float*)s;
#pragma unroll
    for (int e = 0; e < E; e++) f[e * 1024 + tid] = impL[e];
    __syncthreads();
    for (int off = 512; off; off >>= 1) {
        if (tid < off)
#pragma unroll
            for (int e = 0; e < E; e++) f[e * 1024 + tid] += f[e * 1024 + tid + off];
        __syncthreads();
    }
    if (tid == 0) {
        const float Tf = (float)T;
        float penalty_a = g_red[0] / (Tf * (float)E);
        float pb_acc = 0.f;
        for (int e = 0; e < E; e++) { float pm = g_red[1 + e] / Tf; pb_acc += pm * (1.f - pm); }
        float penalty_b = 1.f / (float)E - pb_acc / (float)E;
        float penalty = W_PEN * (penalty_a + penalty_b);
        float z = LAMBDA_Z * g_red[9] / Tf;
        float load = 0.f;
        for (int e = 0; e < E; e++) load += (g_red[18 + e] / Tf) * (g_red[10 + e] / Tf);
        load *= W_LOAD * (float)E;
        float mean = 0.f;
        for (int e = 0; e < E; e++) mean += f[e * 1024];
        mean /= (float)E;
        float var = 0.f;
        for (int e = 0; e < E; e++) { float d = f[e * 1024] - mean; var += d * d; }
        var /= (float)E;
        float imp_loss = W_IMP * var / (mean * mean);
        out[(size_t)T * D] = penalty + z + load + imp_loss;
    }
}

// ---------------- fp16 mma.sync grouped GEMM (KBLK=64, 3-stage ring) ---------
#define KBLK    64
#define STAGES  3
#define A_STRIDE 144                   // 64 halves (128B) + 16B pad
#define A_BYTES (128 * A_STRIDE)       // 18432
#define B_BYTES (KBLK * 256)           // 16384
#define STG_BYTES (A_BYTES + B_BYTES)  // 34816
#define SMEM_BYTES (STAGES * STG_BYTES + 1536)

template <bool IS_FFN1>
__global__ __launch_bounds__(256, 2) void moe_mma(
    const __half* __restrict__ Ag, const __half* __restrict__ Bw,
    const float* __restrict__ biasw, void* __restrict__ Outv,
    int K, int ldA, int Ntot,
    const float* __restrict__ w2src, __half* __restrict__ w2dst,
    float* __restrict__ outz)
{
    if (IS_FFN1 && blockIdx.z >= 2 * E) {
        int b = blockIdx.y * gridDim.x + blockIdx.x;
        int tid = threadIdx.x;
        if (blockIdx.z == 2 * E) {
            size_t base = (size_t)b * 16384 + tid;
#pragma unroll 8
            for (int i = 0; i < 64; i++) {
                size_t cc = base + (size_t)i * 256;
                float4 v = ((const float4*)w2src)[cc];
                ((__half2*)w2dst)[cc * 2]     = __floats2half2_rn(v.x, v.y);
                ((__half2*)w2dst)[cc * 2 + 1] = __floats2half2_rn(v.z, v.w);
            }
        } else {
            size_t base = (size_t)b * 4096 + tid;
            float4 z4 = make_float4(0.f, 0.f, 0.f, 0.f);
#pragma unroll
            for (int i = 0; i < 16; i++)
                ((float4*)outz)[base + (size_t)i * 256] = z4;
        }
        return;
    }

    extern __shared__ char smem[];
    int g = blockIdx.z;
    int cnt = (&g_cnt[0][0])[g];
    int m0 = blockIdx.y * 128;
    if (m0 >= cnt) return;
    int n0 = blockIdx.x * 128;
    int e = g & 7;
    const __half* Bh = Bw + (size_t)e * (size_t)K * Ntot;
    const float* bias = biasw + e * Ntot + n0;

    int tid = threadIdx.x, wid = tid >> 5, lane = tid & 31;
    int*   rows = (int*)(smem + STAGES * STG_BYTES);
    int*   stok = rows + 128;
    float* swt  = (float*)(stok + 128);
    if (tid < 128) {
        int tk = (&g_idx[0][0])[g * CAP + m0 + tid];
        if (IS_FFN1) {
            rows[tid] = tk;
        } else {
            rows[tid] = g * CAP + m0 + tid;
            stok[tid] = tk;
            swt[tid] = (tk >= 0) ? (&g_ws[0][0])[(g >> 3) * T + tk] : 0.f;
        }
    }
    __syncthreads();
    uint32_t sbase = smem_u32(smem);
    int NKB = K / KBLK;

    // stage loader: 2048 x 16B chunks (B:1024, A:1024), 8 per thread
    auto load_stage = [&](int kb, int st) {
        uint32_t sa = sbase + st * STG_BYTES;
        uint32_t sB = sa + A_BYTES;
        int k0 = kb * KBLK;
#pragma unroll
        for (int i = 0; i < 8; i++) {
            int c = tid + i * 256;
            if (c < 1024) {                      // B: 64 k-rows x 128 halves
                int k = c >> 4, nch = c & 15;
                const void* src = Bh + (size_t)(k0 + k) * Ntot + n0 + nch * 8;
                uint32_t dst = sB + k * 256 + (((uint32_t)(nch ^ (k & 7))) << 4);
                cp16(dst, src, 16);
            } else {                             // A: 128 rows x 64 halves
                int c2 = c - 1024, r = c2 >> 3, ch = c2 & 7;
                int tok = rows[r];
                uint32_t ssz = 16;
                if (IS_FFN1 && tok < 0) { tok = 0; ssz = 0; }
                const void* src = Ag + (size_t)tok * ldA + k0 + ch * 8;
                uint32_t dst = sa + r * A_STRIDE + (ch << 4);
                cp16(dst, src, ssz);
            }
        }
        asm volatile("cp.async.commit_group;" ::: "memory");
    };

    int wm = (wid & 3) * 32, wn = (wid >> 2) * 64;
    float acc[2][8][4];
#pragma unroll
    for (int mi = 0; mi < 2; mi++)
#pragma unroll
        for (int ni = 0; ni < 8; ni++)
#pragma unroll
            for (int j = 0; j < 4; j++) acc[mi][ni][j] = 0.f;

    load_stage(0, 0);
    load_stage(1, 1);

    int q = lane >> 3, r8 = lane & 7;
    for (int kb = 0; kb < NKB; kb++) {
        int st = kb % 3;
        if (kb + 1 < NKB)
            asm volatile("cp.async.wait_group 1;" ::: "memory");
        else
            asm volatile("cp.async.wait_group 0;" ::: "memory");
        __syncthreads();
        uint32_t sa = sbase + st * STG_BYTES;
        uint32_t sB = sa + A_BYTES;
#pragma unroll
        for (int ks = 0; ks < 4; ks++) {
            uint32_t af[2][4], bf[8][2];
#pragma unroll
            for (int mi = 0; mi < 2; mi++) {
                int row = wm + mi * 16 + r8 + (q & 1) * 8;
                int ch = ks * 2 + (q >> 1);
                ldsm4(af[mi], sa + row * A_STRIDE + ch * 16);
            }
#pragma unroll
            for (int i = 0; i < 4; i++) {
                int k = ks * 16 + (q & 1) * 8 + r8;
                int nch = (wn >> 3) + i * 2 + (q >> 1);
                uint32_t rr[4];
                ldsm4t(rr, sB + k * 256 + (((uint32_t)(nch ^ (k & 7))) << 4));
                bf[i * 2][0] = rr[0]; bf[i * 2][1] = rr[1];
                bf[i * 2 + 1][0] = rr[2]; bf[i * 2 + 1][1] = rr[3];
            }
#pragma unroll
            for (int mi = 0; mi < 2; mi++)
#pragma unroll
                for (int ni = 0; ni < 8; ni++)
                    mma16816(acc[mi][ni], af[mi], bf[ni]);
        }
        if (kb + 2 < NKB) load_stage(kb + 2, (kb + 2) % 3);
    }

    // epilogue
#pragma unroll
    for (int mi = 0; mi < 2; mi++) {
#pragma unroll
        for (int ni = 0; ni < 8; ni++) {
            int rloc = wm + mi * 16 + (lane >> 2);
            int col = wn + ni * 8 + (lane & 3) * 2;
            float b0 = bias[col], b1 = bias[col + 1];
            float v0 = acc[mi][ni][0] + b0, v1 = acc[mi][ni][1] + b1;
            float v2 = acc[mi][ni][2] + b0, v3 = acc[mi][ni][3] + b1;
            if (IS_FFN1) {
                v0 = gelu_tanh(v0); v1 = gelu_tanh(v1);
                v2 = gelu_tanh(v2); v3 = gelu_tanh(v3);
                __half* Out = (__half*)Outv;
                size_t o = ((size_t)g * CAP + m0 + rloc) * Ntot + n0 + col;
                *(__half2*)(Out + o) = __floats2half2_rn(v0, v1);
                *(__half2*)(Out + o + (size_t)8 * Ntot) = __floats2half2_rn(v2, v3);
            } else {
                float* Out = (float*)Outv;
                int tk0 = stok[rloc];
                if (tk0 >= 0) {
                    float w = swt[rloc];
                    float* p = Out + (size_t)tk0 * D + n0 + col;
                    redadd(p, w * v0); redadd(p + 1, w * v1);
                }
                int tk1 = stok[rloc + 8];
                if (tk1 >= 0) {
                    float w = swt[rloc + 8];
                    float* p = Out + (size_t)tk1 * D + n0 + col;
                    redadd(p, w * v2); redadd(p + 1, w * v3);
                }
            }
        }
    }
}

// ---------------- launcher ---------------------------------------------------
extern "C" void kernel_launch(void* const* d_in, const int* in_sizes, int n_in,
                              void* d_out, int out_size) {
    const float* x   = (const float*)d_in[0];
    const float* gw  = (const float*)d_in[1];
    const float* w1  = (const float*)d_in[2];
    const float* b1  = (const float*)d_in[3];
    const float* w2  = (const float*)d_in[4];
    const float* b2  = (const float*)d_in[5];
    const float* rnd = (const float*)d_in[6];
    float* out = (float*)d_out;

    cudaFuncSetAttribute(moe_mma<true>,
                         cudaFuncAttributeMaxDynamicSharedMemorySize, SMEM_BYTES);
    cudaFuncSetAttribute(moe_mma<false>,
                         cudaFuncAttributeMaxDynamicSharedMemorySize, SMEM_BYTES);

    __half *xh, *w1h, *w2h, *hh;
    cudaGetSymbolAddress((void**)&xh,  g_Xh);
    cudaGetSymbolAddress((void**)&w1h, g_W1h);
    cudaGetSymbolAddress((void**)&w2h, g_W2h);
    cudaGetSymbolAddress((void**)&hh,  g_Hh);

    prologue_kernel<<<GATE_BLKS + F2H_BLKS, 256>>>(x, gw, w1, xh, w1h);
    scan_kernel<<<1, 1024>>>(rnd, out);

    moe_mma<true><<<dim3(FF / 128, CAP / 128, 2 * E + 2), 256, SMEM_BYTES>>>(
        xh, w1h, b1, (void*)hh, D, D, FF, w2, w2h, out);
    moe_mma<false><<<dim3(D / 128, CAP / 128, 2 * E), 256, SMEM_BYTES>>>(
        hh, w2h, b2, (void*)out, FF, FF, D, nullptr, nullptr, nullptr);
}

// round 15
// speedup vs baseline: 1.5356x; 1.5356x over previous
#include <cuda_runtime.h>
#include <cuda_fp16.h>
#include <cstdint>

#define D    1024
#define E    8
#define FF   4096
#define CAP  2048
#define T    8192
#define W_IMP    0.01f
#define W_LOAD   0.01f
#define LAMBDA_Z 0.001f
#define W_PEN    0.01f

// ---------------- device scratch ---------------------------------------------
__device__ int   g_e1[T], g_e2[T];
__device__ float g_g1n[T], g_g2n[T];
__device__ float g_ws[2][T];
__device__ int   g_idx[2][E * CAP];
__device__ int   g_cnt[2][E];
__device__ float g_part[(T / 8) * 26];
__device__ float g_red[26];
__device__ __half g_Hh[(size_t)2 * E * CAP * FF];
__device__ __half g_Xh[(size_t)T * D];
__device__ __half g_W1h[(size_t)E * D * FF];
__device__ __half g_W2h[(size_t)E * FF * D];

// ---------------- helpers ----------------------------------------------------
__device__ __forceinline__ uint32_t smem_u32(const void* p) {
    uint32_t a;
    asm("{ .reg .u64 t; cvta.to.shared.u64 t, %1; cvt.u32.u64 %0, t; }" : "=r"(a) : "l"(p));
    return a;
}
__device__ __forceinline__ float gelu_tanh(float v) {
    const float c = 0.7978845608028654f;
    float u = c * (v + 0.044715f * v * v * v);
    return 0.5f * v * (1.0f + tanhf(u));
}
__device__ __forceinline__ void cp16(uint32_t s, const void* g, uint32_t ssz) {
    asm volatile("cp.async.cg.shared.global [%0], [%1], 16, %2;"
                 :: "r"(s), "l"(g), "r"(ssz));
}
__device__ __forceinline__ void ldsm4(uint32_t* r, uint32_t addr) {
    asm volatile("ldmatrix.sync.aligned.m8n8.x4.shared.b16 {%0,%1,%2,%3}, [%4];"
                 : "=r"(r[0]), "=r"(r[1]), "=r"(r[2]), "=r"(r[3]) : "r"(addr));
}
__device__ __forceinline__ void ldsm4t(uint32_t* r, uint32_t addr) {
    asm volatile("ldmatrix.sync.aligned.m8n8.x4.trans.shared.b16 {%0,%1,%2,%3}, [%4];"
                 : "=r"(r[0]), "=r"(r[1]), "=r"(r[2]), "=r"(r[3]) : "r"(addr));
}
__device__ __forceinline__ void mma16816(float* c, const uint32_t* a, const uint32_t* b) {
    asm volatile("mma.sync.aligned.m16n8k16.row.col.f32.f16.f16.f32 "
                 "{%0,%1,%2,%3}, {%4,%5,%6,%7}, {%8,%9}, {%0,%1,%2,%3};"
                 : "+f"(c[0]), "+f"(c[1]), "+f"(c[2]), "+f"(c[3])
                 : "r"(a[0]), "r"(a[1]), "r"(a[2]), "r"(a[3]), "r"(b[0]), "r"(b[1]));
}
__device__ __forceinline__ void redadd(float* p, float v) {
    asm volatile("red.global.add.f32 [%0], %1;" :: "l"(p), "f"(v) : "memory");
}

// ---------------- gate kernel -------------------------------------------------
__global__ void gate_kernel(const float* __restrict__ x, const float* __restrict__ gw) {
    __shared__ float sgw[E * D];
    __shared__ float wpart[8][26];
    int tid = threadIdx.x;
    for (int i = tid; i < E * D; i += 256) sgw[i] = gw[i];
    __syncthreads();
    int warp = tid >> 5, lane = tid & 31;
    int t = blockIdx.x * 8 + warp;
    float acc[E];
#pragma unroll
    for (int e = 0; e < E; e++) acc[e] = 0.f;
    const float* xr = x + (size_t)t * D;
#pragma unroll 4
    for (int j = 0; j < D / 32; j++) {
        float xv = xr[j * 32 + lane];
#pragma unroll
        for (int e = 0; e < E; e++) acc[e] += xv * sgw[e * D + j * 32 + lane];
    }
#pragma unroll
    for (int e = 0; e < E; e++)
#pragma unroll
        for (int off = 16; off; off >>= 1)
            acc[e] += __shfl_xor_sync(0xffffffffu, acc[e], off);
    float m = acc[0];
#pragma unroll
    for (int e = 1; e < E; e++) m = fmaxf(m, acc[e]);
    float p166[E]; float s166 = 0.f;
#pragma unroll
    for (int e = 0; e < E; e++) { p166[e] = expf((acc[e] - m) / 1.66f); s166 += p166[e]; }
    float pa = 0.f;
#pragma unroll
    for (int e = 0; e < E; e++) { p166[e] /= s166; pa += p166[e] * (1.f - p166[e]); }
    float p[E]; float s = 0.f;
#pragma unroll
    for (int e = 0; e < E; e++) { p[e] = expf(acc[e] - m); s += p[e]; }
    float lse = m + logf(s);
#pragma unroll
    for (int e = 0; e < E; e++) p[e] /= s;
    int e1 = 0; float p1 = p[0];
#pragma unroll
    for (int e = 1; e < E; e++) if (p[e] > p1) { p1 = p[e]; e1 = e; }
    int e2 = -1; float p2 = -1.f;
#pragma unroll
    for (int e = 0; e < E; e++) if (e != e1 && p[e] > p2) { p2 = p[e]; e2 = e; }
    float den = p1 + p2;
    if (lane == 0) {
        g_e1[t] = e1; g_e2[t] = e2;
        g_g1n[t] = p1 / den; g_g2n[t] = p2 / den;
        wpart[warp][0] = pa;
#pragma unroll
        for (int e = 0; e < E; e++) wpart[warp][1 + e] = p166[e];
        wpart[warp][9] = lse * lse;
#pragma unroll
        for (int e = 0; e < E; e++) wpart[warp][10 + e] = p[e];
#pragma unroll
        for (int e = 0; e < E; e++) wpart[warp][18 + e] = (e == e1) ? 1.f : 0.f;
    }
    __syncthreads();
    if (tid < 26) {
        float sum = 0.f;
        for (int w = 0; w < 8; w++) sum += wpart[w][tid];
        g_part[blockIdx.x * 26 + tid] = sum;
    }
}

// ---------------- scan (block 0) + f2h (blocks 1..) --------------------------
#define X4  (T * D / 4)
#define W4  (E * D * FF / 4)
#define F2H_TOTAL (X4 + W4)
#define F2H_BLKS (F2H_TOTAL / 1024)

__global__ void scan_f2h_kernel(const float* __restrict__ rnd, float* __restrict__ out,
                                const float* __restrict__ x, const float* __restrict__ w1,
                                __half* __restrict__ xh, __half* __restrict__ w1h) {
    if (blockIdx.x > 0) {
        // f2h conversion blocks (256 threads, 4 float4 each)
        size_t base = (size_t)(blockIdx.x - 1) * 1024 + threadIdx.x;
#pragma unroll
        for (int i = 0; i < 4; i++) {
            size_t c = base + (size_t)i * 256;
            const float4* src; __half2* dst;
            if (c < X4) { src = (const float4*)x  + c;        dst = (__half2*)xh  + c * 2; }
            else        { src = (const float4*)w1 + (c - X4); dst = (__half2*)w1h + (c - X4) * 2; }
            float4 v = *src;
            dst[0] = __floats2half2_rn(v.x, v.y);
            dst[1] = __floats2half2_rn(v.z, v.w);
        }
        return;
    }
    // ---- block 0: scan + reduce + aux (1024 threads) ----
    __shared__ int s[E][1024];
    int tid = threadIdx.x;
    if (tid < 26) {
        float sum = 0.f;
        for (int b = 0; b < T / 8; b++) sum += g_part[b * 26 + tid];
        g_red[tid] = sum;
    }
    for (int i = tid; i < 2 * E * CAP; i += 1024) ((int*)g_idx)[i] = -1;
    int t0 = tid * 8;

    // slot 1
    int ev[8];
#pragma unroll
    for (int j = 0; j < 8; j++) ev[j] = g_e1[t0 + j];
    int c[E];
#pragma unroll
    for (int e = 0; e < E; e++) c[e] = 0;
#pragma unroll
    for (int j = 0; j < 8; j++) c[ev[j]]++;
#pragma unroll
    for (int e = 0; e < E; e++) s[e][tid] = c[e];
    __syncthreads();
    for (int off = 1; off < 1024; off <<= 1) {
        int r[E];
#pragma unroll
        for (int e = 0; e < E; e++) r[e] = (tid >= off) ? s[e][tid - off] : 0;
        __syncthreads();
#pragma unroll
        for (int e = 0; e < E; e++) s[e][tid] += r[e];
        __syncthreads();
    }
    int excl[E], tot[E];
#pragma unroll
    for (int e = 0; e < E; e++) { excl[e] = s[e][tid] - c[e]; tot[e] = s[e][1023]; }
    float impL[E];
#pragma unroll
    for (int e = 0; e < E; e++) impL[e] = 0.f;
#pragma unroll
    for (int j = 0; j < 8; j++) {
        int t = t0 + j, e = ev[j];
        int p = excl[e]++;
        bool mk = p < CAP;
        float w = mk ? g_g1n[t] : 0.f;
        g_ws[0][t] = w;
        if (mk) g_idx[0][e * CAP + p] = t;
        impL[e] += w;
    }
    if (tid == 0)
        for (int e = 0; e < E; e++) g_cnt[0][e] = tot[e] < CAP ? tot[e] : CAP;
    __syncthreads();

    // slot 2, pass 1: original positions -> masks
#pragma unroll
    for (int j = 0; j < 8; j++) ev[j] = g_e2[t0 + j];
#pragma unroll
    for (int e = 0; e < E; e++) c[e] = 0;
#pragma unroll
    for (int j = 0; j < 8; j++) c[ev[j]]++;
#pragma unroll
    for (int e = 0; e < E; e++) s[e][tid] = c[e];
    __syncthreads();
    for (int off = 1; off < 1024; off <<= 1) {
        int r[E];
#pragma unroll
        for (int e = 0; e < E; e++) r[e] = (tid >= off) ? s[e][tid - off] : 0;
        __syncthreads();
#pragma unroll
        for (int e = 0; e < E; e++) s[e][tid] += r[e];
        __syncthreads();
    }
#pragma unroll
    for (int e = 0; e < E; e++) excl[e] = s[e][tid] - c[e];
    bool live[8];
#pragma unroll
    for (int j = 0; j < 8; j++) {
        int t = t0 + j, e = ev[j];
        int p = excl[e]++;
        float g2n = g_g2n[t];
        bool mk = (p < CAP) && (rnd[t] < 2.f * g2n);
        live[j] = mk;
        float w = mk ? g2n : 0.f;
        g_ws[1][t] = w;
        impL[e] += w;
    }
    __syncthreads();

    // slot 2, pass 2: compacted
#pragma unroll
    for (int e = 0; e < E; e++) c[e] = 0;
#pragma unroll
    for (int j = 0; j < 8; j++) if (live[j]) c[ev[j]]++;
#pragma unroll
    for (int e = 0; e < E; e++) s[e][tid] = c[e];
    __syncthreads();
    for (int off = 1; off < 1024; off <<= 1) {
        int r[E];
#pragma unroll
        for (int e = 0; e < E; e++) r[e] = (tid >= off) ? s[e][tid - off] : 0;
        __syncthreads();
#pragma unroll
        for (int e = 0; e < E; e++) s[e][tid] += r[e];
        __syncthreads();
    }
#pragma unroll
    for (int e = 0; e < E; e++) { excl[e] = s[e][tid] - c[e]; tot[e] = s[e][1023]; }
#pragma unroll
    for (int j = 0; j < 8; j++) {
        if (!live[j]) continue;
        int t = t0 + j, e = ev[j];
        int p = excl[e]++;
        g_idx[1][e * CAP + p] = t;
    }
    if (tid == 0)
        for (int e = 0; e < E; e++) g_cnt[1][e] = tot[e];
    __syncthreads();

    // imp reduction + aux
    float* f = (float*)s;
#pragma unroll
    for (int e = 0; e < E; e++) f[e * 1024 + tid] = impL[e];
    __syncthreads();
    for (int off = 512; off; off >>= 1) {
        if (tid < off)
#pragma unroll
            for (int e = 0; e < E; e++) f[e * 1024 + tid] += f[e * 1024 + tid + off];
        __syncthreads();
    }
    if (tid == 0) {
        const float Tf = (float)T;
        float penalty_a = g_red[0] / (Tf * (float)E);
        float pb_acc = 0.f;
        for (int e = 0; e < E; e++) { float pm = g_red[1 + e] / Tf; pb_acc += pm * (1.f - pm); }
        float penalty_b = 1.f / (float)E - pb_acc / (float)E;
        float penalty = W_PEN * (penalty_a + penalty_b);
        float z = LAMBDA_Z * g_red[9] / Tf;
        float load = 0.f;
        for (int e = 0; e < E; e++) load += (g_red[18 + e] / Tf) * (g_red[10 + e] / Tf);
        load *= W_LOAD * (float)E;
        float mean = 0.f;
        for (int e = 0; e < E; e++) mean += f[e * 1024];
        mean /= (float)E;
        float var = 0.f;
        for (int e = 0; e < E; e++) { float d = f[e * 1024] - mean; var += d * d; }
        var /= (float)E;
        float imp_loss = W_IMP * var / (mean * mean);
        out[(size_t)T * D] = penalty + z + load + imp_loss;
    }
}

// ---------------- fp16 mma.sync grouped GEMM (R10 config: KBLK=32, 3 stages) -
#define KBLK    32
#define STAGES  3
#define A_STRIDE 80
#define A_BYTES (128 * A_STRIDE)
#define B_BYTES (KBLK * 256)
#define STG_BYTES (A_BYTES + B_BYTES)
#define SMEM_BYTES (STAGES * STG_BYTES + 1536)

template <bool IS_FFN1>
__global__ __launch_bounds__(256, 2) void moe_mma(
    const __half* __restrict__ Ag, const __half* __restrict__ Bw,
    const float* __restrict__ biasw, void* __restrict__ Outv,
    int K, int ldA, int Ntot,
    const float* __restrict__ w2src, __half* __restrict__ w2dst,
    float* __restrict__ outz)
{
    if (IS_FFN1 && blockIdx.z >= 2 * E) {
        int b = blockIdx.y * gridDim.x + blockIdx.x;   // 0..511
        int tid = threadIdx.x;
        if (blockIdx.z == 2 * E) {                     // w2 fp32 -> fp16
            size_t base = (size_t)b * 16384 + tid;
#pragma unroll 8
            for (int i = 0; i < 64; i++) {
                size_t cc = base + (size_t)i * 256;
                float4 v = ((const float4*)w2src)[cc];
                ((__half2*)w2dst)[cc * 2]     = __floats2half2_rn(v.x, v.y);
                ((__half2*)w2dst)[cc * 2 + 1] = __floats2half2_rn(v.z, v.w);
            }
        } else {                                       // zero out[0..T*D)
            size_t base = (size_t)b * 4096 + tid;
            float4 z4 = make_float4(0.f, 0.f, 0.f, 0.f);
#pragma unroll
            for (int i = 0; i < 16; i++)
                ((float4*)outz)[base + (size_t)i * 256] = z4;
        }
        return;
    }

    extern __shared__ char smem[];
    int g = blockIdx.z;
    int cnt = (&g_cnt[0][0])[g];
    int m0 = blockIdx.y * 128;
    if (m0 >= cnt) return;
    int n0 = blockIdx.x * 128;
    int e = g & 7;
    const __half* Bh = Bw + (size_t)e * (size_t)K * Ntot;
    const float* bias = biasw + e * Ntot + n0;

    int tid = threadIdx.x, wid = tid >> 5, lane = tid & 31;
    int*   rows = (int*)(smem + STAGES * STG_BYTES);
    int*   stok = rows + 128;
    float* swt  = (float*)(stok + 128);
    if (tid < 128) {
        int tk = (&g_idx[0][0])[g * CAP + m0 + tid];
        if (IS_FFN1) {
            rows[tid] = tk;
        } else {
            rows[tid] = g * CAP + m0 + tid;
            stok[tid] = tk;
            swt[tid] = (tk >= 0) ? (&g_ws[0][0])[(g >> 3) * T + tk] : 0.f;
        }
    }
    __syncthreads();
    uint32_t sbase = smem_u32(smem);
    int NKB = K / KBLK;

    auto load_stage = [&](int kb, int st) {
        uint32_t sa = sbase + st * STG_BYTES;
        uint32_t sB = sa + A_BYTES;
        int k0 = kb * KBLK;
#pragma unroll
        for (int i = 0; i < 4; i++) {
            int c = tid + i * 256;
            if (c < 512) {
                int k = c >> 4, nch = c & 15;
                const void* src = Bh + (size_t)(k0 + k) * Ntot + n0 + nch * 8;
                uint32_t dst = sB + k * 256 + (((uint32_t)(nch ^ (k & 7))) << 4);
                cp16(dst, src, 16);
            } else {
                int c2 = c - 512, r = c2 >> 2, ch = c2 & 3;
                int tok = rows[r];
                uint32_t ssz = 16;
                if (IS_FFN1 && tok < 0) { tok = 0; ssz = 0; }
                const void* src = Ag + (size_t)tok * ldA + k0 + ch * 8;
                uint32_t dst = sa + r * A_STRIDE + (ch << 4);
                cp16(dst, src, ssz);
            }
        }
        asm volatile("cp.async.commit_group;" ::: "memory");
    };

    int wm = (wid & 3) * 32, wn = (wid >> 2) * 64;
    float acc[2][8][4];
#pragma unroll
    for (int mi = 0; mi < 2; mi++)
#pragma unroll
        for (int ni = 0; ni < 8; ni++)
#pragma unroll
            for (int j = 0; j < 4; j++) acc[mi][ni][j] = 0.f;

    load_stage(0, 0);
    load_stage(1, 1);

    int q = lane >> 3, r8 = lane & 7;
    for (int kb = 0; kb < NKB; kb++) {
        int st = kb % 3;
        if (kb + 1 < NKB)
            asm volatile("cp.async.wait_group 1;" ::: "memory");
        else
            asm volatile("cp.async.wait_group 0;" ::: "memory");
        __syncthreads();
        uint32_t sa = sbase + st * STG_BYTES;
        uint32_t sB = sa + A_BYTES;
#pragma unroll
        for (int ks = 0; ks < 2; ks++) {
            uint32_t af[2][4], bf[8][2];
#pragma unroll
            for (int mi = 0; mi < 2; mi++) {
                int row = wm + mi * 16 + r8 + (q & 1) * 8;
                int ch = ks * 2 + (q >> 1);
                ldsm4(af[mi], sa + row * A_STRIDE + ch * 16);
            }
#pragma unroll
            for (int i = 0; i < 4; i++) {
                int k = ks * 16 + (q & 1) * 8 + r8;
                int nch = (wn >> 3) + i * 2 + (q >> 1);
                uint32_t rr[4];
                ldsm4t(rr, sB + k * 256 + (((uint32_t)(nch ^ (k & 7))) << 4));
                bf[i * 2][0] = rr[0]; bf[i * 2][1] = rr[1];
                bf[i * 2 + 1][0] = rr[2]; bf[i * 2 + 1][1] = rr[3];
            }
#pragma unroll
            for (int mi = 0; mi < 2; mi++)
#pragma unroll
                for (int ni = 0; ni < 8; ni++)
                    mma16816(acc[mi][ni], af[mi], bf[ni]);
        }
        if (kb + 2 < NKB) load_stage(kb + 2, (kb + 2) % 3);
    }

    // epilogue
#pragma unroll
    for (int mi = 0; mi < 2; mi++) {
#pragma unroll
        for (int ni = 0; ni < 8; ni++) {
            int rloc = wm + mi * 16 + (lane >> 2);
            int col = wn + ni * 8 + (lane & 3) * 2;
            float b0 = bias[col], b1 = bias[col + 1];
            float v0 = acc[mi][ni][0] + b0, v1 = acc[mi][ni][1] + b1;
            float v2 = acc[mi][ni][2] + b0, v3 = acc[mi][ni][3] + b1;
            if (IS_FFN1) {
                v0 = gelu_tanh(v0); v1 = gelu_tanh(v1);
                v2 = gelu_tanh(v2); v3 = gelu_tanh(v3);
                __half* Out = (__half*)Outv;
                size_t o = ((size_t)g * CAP + m0 + rloc) * Ntot + n0 + col;
                *(__half2*)(Out + o) = __floats2half2_rn(v0, v1);
                *(__half2*)(Out + o + (size_t)8 * Ntot) = __floats2half2_rn(v2, v3);
            } else {
                float* Out = (float*)Outv;
                int tk0 = stok[rloc];
                if (tk0 >= 0) {
                    float w = swt[rloc];
                    float* p = Out + (size_t)tk0 * D + n0 + col;
                    redadd(p, w * v0); redadd(p + 1, w * v1);
                }
                int tk1 = stok[rloc + 8];
                if (tk1 >= 0) {
                    float w = swt[rloc + 8];
                    float* p = Out + (size_t)tk1 * D + n0 + col;
                    redadd(p, w * v2); redadd(p + 1, w * v3);
                }
            }
        }
    }
}

// ---------------- launcher ---------------------------------------------------
extern "C" void kernel_launch(void* const* d_in, const int* in_sizes, int n_in,
                              void* d_out, int out_size) {
    const float* x   = (const float*)d_in[0];
    const float* gw  = (const float*)d_in[1];
    const float* w1  = (const float*)d_in[2];
    const float* b1  = (const float*)d_in[3];
    const float* w2  = (const float*)d_in[4];
    const float* b2  = (const float*)d_in[5];
    const float* rnd = (const float*)d_in[6];
    float* out = (float*)d_out;

    cudaFuncSetAttribute(moe_mma<true>,
                         cudaFuncAttributeMaxDynamicSharedMemorySize, SMEM_BYTES);
    cudaFuncSetAttribute(moe_mma<false>,
                         cudaFuncAttributeMaxDynamicSharedMemorySize, SMEM_BYTES);

    __half *xh, *w1h, *w2h, *hh;
    cudaGetSymbolAddress((void**)&xh,  g_Xh);
    cudaGetSymbolAddress((void**)&w1h, g_W1h);
    cudaGetSymbolAddress((void**)&w2h, g_W2h);
    cudaGetSymbolAddress((void**)&hh,  g_Hh);

    gate_kernel<<<T / 8, 256>>>(x, gw);
    scan_f2h_kernel<<<1 + F2H_BLKS, 1024>>>(rnd, out, x, w1, xh, w1h);

    moe_mma<true><<<dim3(FF / 128, CAP / 128, 2 * E + 2), 256, SMEM_BYTES>>>(
        xh, w1h, b1, (void*)hh, D, D, FF, w2, w2h, out);
    moe_mma<false><<<dim3(D / 128, CAP / 128, 2 * E), 256, SMEM_BYTES>>>(
        hh, w2h, b2, (void*)out, FF, FF, D, nullptr, nullptr, nullptr);
}